// round 14
// baseline (speedup 1.0000x reference)
#include <cuda_runtime.h>

// PixelShuffle / depth-to-space, R=2, feature-major grouping.
// in : [B=8, X=256, Y=256, C=256] fp32
// out: [B, 2X=512, 2Y=512, F=64]  fp32
// out[b, 2x+i, 2y+j, f] = in[b, x, y, 4f + 2i + j]
//
// COMMITTED FINAL (reproduced 3x: kernel 148.4-148.9us, DRAM 86.3-86.7%,
// HBM ~6.87TB/s = 86% of spec; wall 156.1-157.1us).
//  - 16 threads/pixel: thread t loads channels [16t,16t+16) as 4x LDG.128
//    front-batched (warp = 2KB contiguous read), writes 4x STG.128, one per
//    (i,j) phase (1KB contiguous run per i-phase per warp). Every 32B sector
//    of both streams fully used. regs 34.
//  - 128-thread CTAs: measured CTA-granularity optimum (256t/128t/64t swept).
// Traffic is the exact permutation minimum (1 GiB); absolute floor at spec
// is ~134us. Limiter: HBM controller read/write turnaround on the 1:1
// streaming mix; all SM pipes <=7% busy. Full lever sweep (8 variants):
// .cs hints regress (L1 churn); persistent loop regresses (serializes MLP);
// v8 256-bit ops regress (L2 up); MLP 4 vs 8 neutral; occ 49-80% neutral;
// 1KB vs 2KB write runs neutral. No SASS-level change moves the ceiling.

static constexpr int X = 256;
static constexpr int Y = 256;
static constexpr int C = 256;   // = 64 features * 4
static constexpr int THREADS = 128;

__global__ void pixel_shuffle_kernel(const float4* __restrict__ in,
                                     float4* __restrict__ out) {
    const unsigned g = blockIdx.x * THREADS + threadIdx.x;

    const unsigned t = g & 15u;           // 16-channel chunk within pixel
    const unsigned p = g >> 4;            // input pixel id: b*65536 + x*256 + y

    const unsigned y = p & 255u;
    const unsigned x = (p >> 8) & 255u;
    const unsigned b = p >> 16;

    // ---- load: 16 contiguous channels = 4 float4, front-batched ----
    const float4* ip = in + (size_t)p * (C / 4) + t * 4;
    const float4 v0 = ip[0];
    const float4 v1 = ip[1];
    const float4 v2 = ip[2];
    const float4 v3 = ip[3];

    // v{k}.c = channel 16t + 4k + c  (feature 4t+k, phase c = 2i + j)

    // ---- store: one float4 per (i,j) output row ----
    // out float4 index: base = ((b*512 + 2x)*512 + 2y)*16 + t
    const unsigned obase = (((b * (2 * X) + 2 * x) * (2 * Y)) + 2 * y) * 16 + t;
    const unsigned ROWI = (2 * Y) * 16;   // +i stride (one output X-row)
    const unsigned ROWJ = 16;             // +j stride (one output Y-row)

    out[obase]               = make_float4(v0.x, v1.x, v2.x, v3.x); // i=0,j=0
    out[obase + ROWJ]        = make_float4(v0.y, v1.y, v2.y, v3.y); // i=0,j=1
    out[obase + ROWI]        = make_float4(v0.z, v1.z, v2.z, v3.z); // i=1,j=0
    out[obase + ROWI + ROWJ] = make_float4(v0.w, v1.w, v2.w, v3.w); // i=1,j=1
}

extern "C" void kernel_launch(void* const* d_in, const int* in_sizes, int n_in,
                              void* d_out, int out_size) {
    (void)n_in; (void)out_size;
    const float4* in = (const float4*)d_in[0];
    float4* out = (float4*)d_out;

    const long long total_threads = (long long)in_sizes[0] / 16;  // 16 floats/thread
    const int grid = (int)(total_threads / THREADS);              // exact: power of 2

    pixel_shuffle_kernel<<<grid, THREADS>>>(in, out);
}

// round 15
// speedup vs baseline: 1.0072x; 1.0072x over previous
#include <cuda_runtime.h>

// PixelShuffle / depth-to-space, R=2, feature-major grouping.
// in : [B=8, X=256, Y=256, C=256] fp32
// out: [B, 2X=512, 2Y=512, F=64]  fp32
// out[b, 2x+i, 2y+j, f] = in[b, x, y, 4f + 2i + j]
//
// FROZEN FINAL (reproduced 4x: kernel 148.4-149.1us, DRAM 86.2-86.7%,
// HBM ~6.85TB/s = 86% of spec; wall 156.1-157.3us).
//  - 16 threads/pixel: thread t loads channels [16t,16t+16) as 4x LDG.128
//    front-batched (warp = 2KB contiguous read), writes 4x STG.128, one per
//    (i,j) phase (1KB contiguous run per i-phase per warp). Every 32B sector
//    of both streams fully used. regs 34.
//  - 128-thread CTAs: measured CTA-granularity optimum (256t/128t/64t swept).
// Traffic is the exact permutation minimum (1 GiB); floor at spec ~134us.
// Limiter: HBM controller read/write turnaround on the 1:1 streaming mix;
// all SM pipes <=7% busy. Full lever sweep: .cs hints regress (L1 churn);
// persistent loop regresses (serializes MLP); v8 256-bit ops regress (L2 up);
// MLP 4 vs 8 neutral; occ 49-80% neutral; 1KB vs 2KB write runs neutral;
// CTA size 128 optimal. Rejected by model: block swizzle (hurts row-buffer
// locality; striding not a B300 lever), scratch two-pass (2x traffic).

static constexpr int X = 256;
static constexpr int Y = 256;
static constexpr int C = 256;   // = 64 features * 4
static constexpr int THREADS = 128;

__global__ void pixel_shuffle_kernel(const float4* __restrict__ in,
                                     float4* __restrict__ out) {
    const unsigned g = blockIdx.x * THREADS + threadIdx.x;

    const unsigned t = g & 15u;           // 16-channel chunk within pixel
    const unsigned p = g >> 4;            // input pixel id: b*65536 + x*256 + y

    const unsigned y = p & 255u;
    const unsigned x = (p >> 8) & 255u;
    const unsigned b = p >> 16;

    // ---- load: 16 contiguous channels = 4 float4, front-batched ----
    const float4* ip = in + (size_t)p * (C / 4) + t * 4;
    const float4 v0 = ip[0];
    const float4 v1 = ip[1];
    const float4 v2 = ip[2];
    const float4 v3 = ip[3];

    // v{k}.c = channel 16t + 4k + c  (feature 4t+k, phase c = 2i + j)

    // ---- store: one float4 per (i,j) output row ----
    // out float4 index: base = ((b*512 + 2x)*512 + 2y)*16 + t
    const unsigned obase = (((b * (2 * X) + 2 * x) * (2 * Y)) + 2 * y) * 16 + t;
    const unsigned ROWI = (2 * Y) * 16;   // +i stride (one output X-row)
    const unsigned ROWJ = 16;             // +j stride (one output Y-row)

    out[obase]               = make_float4(v0.x, v1.x, v2.x, v3.x); // i=0,j=0
    out[obase + ROWJ]        = make_float4(v0.y, v1.y, v2.y, v3.y); // i=0,j=1
    out[obase + ROWI]        = make_float4(v0.z, v1.z, v2.z, v3.z); // i=1,j=0
    out[obase + ROWI + ROWJ] = make_float4(v0.w, v1.w, v2.w, v3.w); // i=1,j=1
}

extern "C" void kernel_launch(void* const* d_in, const int* in_sizes, int n_in,
                              void* d_out, int out_size) {
    (void)n_in; (void)out_size;
    const float4* in = (const float4*)d_in[0];
    float4* out = (float4*)d_out;

    const long long total_threads = (long long)in_sizes[0] / 16;  // 16 floats/thread
    const int grid = (int)(total_threads / THREADS);              // exact: power of 2

    pixel_shuffle_kernel<<<grid, THREADS>>>(in, out);
}